// round 11
// baseline (speedup 1.0000x reference)
#include <cuda_runtime.h>
#include <cuda_fp16.h>
#include <math.h>
#include <stdint.h>

// Problem constants
#define B_   2
#define S_   4096
#define H_   2048
#define NH_  16
#define D_   128
#define NC_  64          // S_/64
#define M_   (B_*S_)     // 8192
#define KTOT 2048

// ---------------------------------------------------------------------------
// Scratch (device globals -- allocation-free per harness rules)
// ---------------------------------------------------------------------------
__device__ __half g_qh[(size_t)B_*NH_*S_*D_];   // fp16 [bh][s][d]
__device__ __half g_kh[(size_t)B_*NH_*S_*D_];
__device__ __half g_vh[(size_t)M_*H_];          // fp16 flat
__device__ __half g_bb[(size_t)M_*H_];
__device__ float  g_o[(size_t)M_*H_];           // intra-chunk attn, fp32 flat
__device__ float  g_P[(size_t)B_*NH_*NC_*D_*D_];// per-chunk outer products (fp32)
__device__ __half g_Sh[(size_t)B_*NH_*NC_*D_*D_];// exclusive-prefix states (fp16)
__device__ __half g_xh[(size_t)M_*H_];          // fp16 activations (x)
__device__ __half g_oh[(size_t)M_*H_];          // fp16 attn (final, for out proj)
__device__ __half g_Wth[5ull*H_*H_];            // transposed weights [N][K] * 64

// ---------------------------------------------------------------------------
// PTX helpers (baseline sm_80+ only; harness targets plain sm_100)
// ---------------------------------------------------------------------------
__device__ __forceinline__ uint32_t s2u(const void* p) {
    uint32_t a;
    asm("{ .reg .u64 t; cvta.to.shared.u64 t, %1; cvt.u32.u64 %0, t; }"
        : "=r"(a) : "l"(p));
    return a;
}

#define CPA(dst, src) \
    asm volatile("cp.async.cg.shared.global [%0], [%1], 16;" :: "r"(dst), "l"(src))
#define CPA_COMMIT() asm volatile("cp.async.commit_group;" ::: "memory")

__device__ __forceinline__ void ldmA(uint32_t (&a)[4], uint32_t addr) {
    asm volatile("ldmatrix.sync.aligned.m8n8.x4.shared.b16 {%0,%1,%2,%3}, [%4];"
                 : "=r"(a[0]), "=r"(a[1]), "=r"(a[2]), "=r"(a[3]) : "r"(addr));
}
__device__ __forceinline__ void ldmAT(uint32_t (&a)[4], uint32_t addr) {
    asm volatile("ldmatrix.sync.aligned.m8n8.x4.trans.shared.b16 {%0,%1,%2,%3}, [%4];"
                 : "=r"(a[0]), "=r"(a[1]), "=r"(a[2]), "=r"(a[3]) : "r"(addr));
}
__device__ __forceinline__ void ldmB(uint32_t (&b)[2], uint32_t addr) {
    asm volatile("ldmatrix.sync.aligned.m8n8.x2.shared.b16 {%0,%1}, [%2];"
                 : "=r"(b[0]), "=r"(b[1]) : "r"(addr));
}
__device__ __forceinline__ void ldmBT(uint32_t (&b)[2], uint32_t addr) {
    asm volatile("ldmatrix.sync.aligned.m8n8.x2.trans.shared.b16 {%0,%1}, [%2];"
                 : "=r"(b[0]), "=r"(b[1]) : "r"(addr));
}
// fp32-accumulate mma (scan kernels)
__device__ __forceinline__ void mma16816(float (&c)[4], const uint32_t (&a)[4],
                                         const uint32_t (&b)[2]) {
    asm volatile(
        "mma.sync.aligned.m16n8k16.row.col.f32.f16.f16.f32 "
        "{%0,%1,%2,%3}, {%4,%5,%6,%7}, {%8,%9}, {%0,%1,%2,%3};"
        : "+f"(c[0]), "+f"(c[1]), "+f"(c[2]), "+f"(c[3])
        : "r"(a[0]), "r"(a[1]), "r"(a[2]), "r"(a[3]), "r"(b[0]), "r"(b[1]));
}
// fp16-accumulate mma, C = 0 init
__device__ __forceinline__ void mmah_z(uint32_t (&d)[2], const uint32_t (&a)[4],
                                       const uint32_t (&b)[2]) {
    asm volatile(
        "mma.sync.aligned.m16n8k16.row.col.f16.f16.f16.f16 "
        "{%0,%1}, {%2,%3,%4,%5}, {%6,%7}, {%8,%9};"
        : "=r"(d[0]), "=r"(d[1])
        : "r"(a[0]), "r"(a[1]), "r"(a[2]), "r"(a[3]), "r"(b[0]), "r"(b[1]),
          "r"(0u), "r"(0u));
}
// fp16-accumulate mma, accumulate into d
__device__ __forceinline__ void mmah(uint32_t (&d)[2], const uint32_t (&a)[4],
                                     const uint32_t (&b)[2]) {
    asm volatile(
        "mma.sync.aligned.m16n8k16.row.col.f16.f16.f16.f16 "
        "{%0,%1}, {%2,%3,%4,%5}, {%6,%7}, {%0,%1};"
        : "+r"(d[0]), "+r"(d[1])
        : "r"(a[0]), "r"(a[1]), "r"(a[2]), "r"(a[3]), "r"(b[0]), "r"(b[1]));
}

// ---------------------------------------------------------------------------
// GEMM core: acc = A @ B^T over K=2048. fp16-accumulate mma chained over
// K=32 (one t-iter), promoted to fp32 registers each t-iter.
// CTA tile 128x128, 256 threads (8 warps: 4M x 2N), BK=32, 3-stage cp.async.
// ---------------------------------------------------------------------------
#define BKC 32
#define KT_ (KTOT / BKC)
#define PITCH 80
#define MAT_BYTES (128 * PITCH)
#define STAGE_BYTES (2 * MAT_BYTES)
#define GEMM_SMEM (3 * STAGE_BYTES)
#define OSCL 0.015625f

__device__ __forceinline__ void gemm_core(
    const __half* __restrict__ Aph, const __half* __restrict__ Bph,
    uint32_t sbase, int tid, float (&acc)[2][8][4])
{
    const int lane = tid & 31, wid = tid >> 5;
    const int wm = wid >> 1, wn = wid & 1;

    auto load_stage = [&](int t) {
        uint32_t sb = sbase + (uint32_t)(t % 3) * STAGE_BYTES;
        const int k0 = t * BKC;
#pragma unroll
        for (int i = 0; i < 2; i++) {
            int v = tid + i * 256;
            int r = v >> 2, c = v & 3;
            uint32_t so = r * PITCH + c * 16;
            size_t go = (size_t)r * KTOT + k0 + c * 8;
            CPA(sb + so,             Aph + go);
            CPA(sb + MAT_BYTES + so, Bph + go);
        }
        CPA_COMMIT();
    };

    load_stage(0);
    load_stage(1);

    const int arow = lane & 15, achk = lane >> 4;
    const int brow = lane & 7,  bchk = (lane >> 3) & 1;

    for (int t = 0; t < KT_; t++) {
        if (t + 1 < KT_) asm volatile("cp.async.wait_group 1;" ::: "memory");
        else             asm volatile("cp.async.wait_group 0;" ::: "memory");
        __syncthreads();
        if (t + 2 < KT_) load_stage(t + 2);

        const uint32_t sb = sbase + (uint32_t)(t % 3) * STAGE_BYTES;

        // preload A fragments for both K halves
        uint32_t ah[2][2][4];
#pragma unroll
        for (int ks = 0; ks < 2; ks++)
#pragma unroll
            for (int mi = 0; mi < 2; mi++)
                ldmA(ah[ks][mi],
                     sb + (uint32_t)(wm * 32 + mi * 16 + arow) * PITCH
                        + ks * 32 + achk * 16);

#pragma unroll
        for (int nn = 0; nn < 4; nn++) {
#pragma unroll
            for (int q = 0; q < 2; q++) {
                int ni = nn * 2 + q;
                uint32_t rb = sb + MAT_BYTES
                            + (uint32_t)(wn * 64 + ni * 8 + brow) * PITCH
                            + bchk * 16;
                uint32_t bf0[2], bf1[2];
                ldmB(bf0, rb);
                ldmB(bf1, rb + 32);
#pragma unroll
                for (int mi = 0; mi < 2; mi++) {
                    uint32_t hh[2];
                    mmah_z(hh, ah[0][mi], bf0);
                    mmah(hh, ah[1][mi], bf1);
                    float2 lo = __half22float2(*(__half2*)&hh[0]);
                    float2 hi = __half22float2(*(__half2*)&hh[1]);
                    acc[mi][ni][0] += lo.x;
                    acc[mi][ni][1] += lo.y;
                    acc[mi][ni][2] += hi.x;
                    acc[mi][ni][3] += hi.y;
                }
            }
        }
    }
}

// Fused 4-projection GEMM: z in {0:q, 1:k, 2:v, 3:b}. Outputs fp16.
__global__ __launch_bounds__(256, 2) void tcgemm_proj(
    const __half* __restrict__ Ah, const __half* __restrict__ Wth,
    __half* __restrict__ Cq, __half* __restrict__ Ck,
    __half* __restrict__ Cv, __half* __restrict__ Cb)
{
    extern __shared__ char smem[];
    const uint32_t sbase = s2u(smem);
    const int tid = threadIdx.x;
    const int lane = tid & 31, wid = tid >> 5;
    const int wm = wid >> 1, wn = wid & 1;
    const int bx = blockIdx.x, by = blockIdx.y, z = blockIdx.z;
    const size_t WSZ = (size_t)H_ * H_;

    float acc[2][8][4];
#pragma unroll
    for (int mi = 0; mi < 2; mi++)
#pragma unroll
        for (int ni = 0; ni < 8; ni++)
#pragma unroll
            for (int j = 0; j < 4; j++) acc[mi][ni][j] = 0.f;

    gemm_core(Ah + (size_t)(by * 128) * KTOT,
              Wth + z * WSZ + (size_t)(bx * 128) * KTOT,
              sbase, tid, acc);

    __half* C = (z == 0) ? Cq : (z == 1) ? Ck : (z == 2) ? Cv : Cb;
    const bool headlay = (z < 2);
#pragma unroll
    for (int mi = 0; mi < 2; mi++) {
        int r0 = by * 128 + wm * 32 + mi * 16 + (lane >> 2);
#pragma unroll
        for (int ni = 0; ni < 8; ni++) {
            int cc = wn * 64 + ni * 8 + (lane & 3) * 2;
            __half2 lo = __floats2half2_rn(acc[mi][ni][0] * OSCL, acc[mi][ni][1] * OSCL);
            __half2 hi = __floats2half2_rn(acc[mi][ni][2] * OSCL, acc[mi][ni][3] * OSCL);
            if (!headlay) {
                __half* p = C + (size_t)r0 * H_ + bx * 128 + cc;
                *(__half2*)p = lo;
                *(__half2*)(p + 8 * H_) = hi;
            } else {
                int b = r0 >> 12, s = r0 & (S_ - 1);
                size_t base = ((size_t)(b * NH_ + bx) * S_ + s) * D_ + cc;
                *(__half2*)(C + base) = lo;
                *(__half2*)(C + base + 8 * D_) = hi;
            }
        }
    }
}

// Output projection GEMM: fp32 result
__global__ __launch_bounds__(256, 2) void tcgemm_out(
    const __half* __restrict__ Ah, const __half* __restrict__ Bh,
    float* __restrict__ C)
{
    extern __shared__ char smem[];
    const uint32_t sbase = s2u(smem);
    const int tid = threadIdx.x;
    const int lane = tid & 31, wid = tid >> 5;
    const int wm = wid >> 1, wn = wid & 1;
    const int bx = blockIdx.x, by = blockIdx.y;

    float acc[2][8][4];
#pragma unroll
    for (int mi = 0; mi < 2; mi++)
#pragma unroll
        for (int ni = 0; ni < 8; ni++)
#pragma unroll
            for (int j = 0; j < 4; j++) acc[mi][ni][j] = 0.f;

    gemm_core(Ah + (size_t)(by * 128) * KTOT,
              Bh + (size_t)(bx * 128) * KTOT, sbase, tid, acc);

#pragma unroll
    for (int mi = 0; mi < 2; mi++) {
        int r0 = by * 128 + wm * 32 + mi * 16 + (lane >> 2);
#pragma unroll
        for (int ni = 0; ni < 8; ni++) {
            int cc = wn * 64 + ni * 8 + (lane & 3) * 2;
            float* p = C + (size_t)r0 * H_ + bx * 128 + cc;
            *(float2*)p = make_float2(acc[mi][ni][0] * OSCL, acc[mi][ni][1] * OSCL);
            *(float2*)(p + 8 * H_) = make_float2(acc[mi][ni][2] * OSCL, acc[mi][ni][3] * OSCL);
        }
    }
}

// ---------------------------------------------------------------------------
// fp32 -> fp16 convert (x only)
// ---------------------------------------------------------------------------
struct alignas(8) hf4 { __half v[4]; };

__global__ __launch_bounds__(256) void convert_half(
    const float* __restrict__ in, __half* __restrict__ out)
{
    size_t v = (size_t)blockIdx.x * 256 + threadIdx.x;
    float4 x = *(const float4*)(in + v * 4);
    hf4 h;
    h.v[0] = __float2half_rn(x.x);
    h.v[1] = __float2half_rn(x.y);
    h.v[2] = __float2half_rn(x.z);
    h.v[3] = __float2half_rn(x.w);
    *(hf4*)(out + v * 4) = h;
}

// ---------------------------------------------------------------------------
// Fused weight transpose + scale(64) + fp16 convert: all 5 weights via z
// ---------------------------------------------------------------------------
__global__ __launch_bounds__(256) void transpose5(
    const float* __restrict__ W0, const float* __restrict__ W1,
    const float* __restrict__ W2, const float* __restrict__ W3,
    const float* __restrict__ W4, __half* __restrict__ outh)
{
    __shared__ float t[32][33];
    const int z = blockIdx.z;
    const float* in = (z == 0) ? W0 : (z == 1) ? W1 : (z == 2) ? W2
                    : (z == 3) ? W3 : W4;
    const size_t WSZ = (size_t)H_ * H_;
    outh += z * WSZ;

    int x = blockIdx.x * 32 + threadIdx.x;
    int y = blockIdx.y * 32 + threadIdx.y;
#pragma unroll
    for (int i = 0; i < 32; i += 8)
        t[threadIdx.y + i][threadIdx.x] = in[(size_t)(y + i) * H_ + x];
    __syncthreads();
    x = blockIdx.y * 32 + threadIdx.x;
    y = blockIdx.x * 32 + threadIdx.y;
#pragma unroll
    for (int i = 0; i < 32; i += 8)
        outh[(size_t)(y + i) * H_ + x] =
            __float2half_rn(t[threadIdx.x][threadIdx.y + i] * 64.0f);
}

// ---------------------------------------------------------------------------
// Tensorized per-chunk local work (fp16 mma), ewise u = sigmoid(b)*v fused:
//   att = tril(q k^T); o_intra = att @ u; P = u^T k
// ---------------------------------------------------------------------------
#define PH 272    // bytes per 128-half row (conflict-free ldmatrix)
#define PA 144    // bytes per 64-half att row
#define CL_SMEM (3 * 64 * PH + 64 * PA)

__global__ __launch_bounds__(256) void chunk_local(
    const __half* __restrict__ q, const __half* __restrict__ k,
    const __half* __restrict__ vh, const __half* __restrict__ bbp,
    float* __restrict__ o, float* __restrict__ P)
{
    extern __shared__ char smc[];
    const uint32_t sq = s2u(smc);
    const uint32_t sk = sq + 64 * PH;
    const uint32_t su = sk + 64 * PH;
    const uint32_t sa = su + 64 * PH;

    const int n = blockIdx.x, bh = blockIdx.y;
    const int tid = threadIdx.x;
    const int lane = tid & 31, wid = tid >> 5;
    const int wm = wid >> 1, wn = wid & 1;
    const int b = bh >> 4, h = bh & 15;
    const size_t gbase = ((size_t)bh * S_ + n * 64) * D_;
    const size_t fbase = ((size_t)(b * S_ + n * 64)) * H_ + h * 128;

    // load q,k tiles; compute u = sigmoid(b)*v on the fly
#pragma unroll
    for (int i = 0; i < 4; i++) {
        int v = tid + i * 256;
        int r = v >> 4, c = v & 15;
        size_t go = gbase + r * 128 + c * 8;
        uint32_t so = r * PH + c * 16;
        *(float4*)(smc + so)                 = *(const float4*)(q + go);
        *(float4*)(smc + 64 * PH + so)       = *(const float4*)(k + go);
        size_t fo = fbase + (size_t)r * H_ + c * 8;
        float4 vv4 = *(const float4*)(vh + fo);
        float4 bb4 = *(const float4*)(bbp + fo);
        const __half2* vp = (const __half2*)&vv4;
        const __half2* bp = (const __half2*)&bb4;
        float4 u4;
        __half2* up = (__half2*)&u4;
#pragma unroll
        for (int jj = 0; jj < 4; jj++) {
            float2 vf = __half22float2(vp[jj]);
            float2 bf = __half22float2(bp[jj]);
            up[jj] = __floats2half2_rn(vf.x / (1.f + expf(-bf.x)),
                                       vf.y / (1.f + expf(-bf.y)));
        }
        *(float4*)(smc + 2 * 64 * PH + so) = u4;
    }
    __syncthreads();

    const int r = lane >> 2, cb = (lane & 3) * 2;

    // ---- att = tril(q k^T): warp tile 16(m=i) x 32(n=j) ----
    {
        float a[4][4] = {};
#pragma unroll
        for (int ks = 0; ks < 8; ks++) {
            uint32_t af[4];
            ldmA(af, sq + (uint32_t)(wm * 16 + (lane & 15)) * PH
                       + ks * 32 + (lane >> 4) * 16);
#pragma unroll
            for (int nf = 0; nf < 4; nf++) {
                uint32_t bf[2];
                ldmB(bf, sk + (uint32_t)(wn * 32 + nf * 8 + (lane & 7)) * PH
                           + ks * 32 + ((lane >> 3) & 1) * 16);
                mma16816(a[nf], af, bf);
            }
        }
#pragma unroll
        for (int nf = 0; nf < 4; nf++) {
            int row0 = wm * 16 + r, row1 = row0 + 8;
            int col = wn * 32 + nf * 8 + cb;
            float c0 = (col     <= row0) ? a[nf][0] : 0.f;
            float c1 = (col + 1 <= row0) ? a[nf][1] : 0.f;
            float c2 = (col     <= row1) ? a[nf][2] : 0.f;
            float c3 = (col + 1 <= row1) ? a[nf][3] : 0.f;
            *(__half2*)(smc + (sa - sq) + row0 * PA + col * 2) = __floats2half2_rn(c0, c1);
            *(__half2*)(smc + (sa - sq) + row1 * PA + col * 2) = __floats2half2_rn(c2, c3);
        }
    }
    __syncthreads();

    // ---- o_intra = att @ u: warp tile 16(m=i) x 64(n=d) ----
    {
        float oacc[8][4] = {};
#pragma unroll
        for (int ks = 0; ks < 4; ks++) {
            uint32_t af[4];
            ldmA(af, sa + (uint32_t)(wm * 16 + (lane & 15)) * PA
                       + ks * 32 + (lane >> 4) * 16);
#pragma unroll
            for (int nf = 0; nf < 8; nf++) {
                int dbase = wn * 64 + nf * 8;
                uint32_t bf[2];
                ldmBT(bf, su + (uint32_t)(ks * 16 + (lane & 15)) * PH + dbase * 2);
                mma16816(oacc[nf], af, bf);
            }
        }
#pragma unroll
        for (int nf = 0; nf < 8; nf++) {
            int d = wn * 64 + nf * 8 + cb;
            int i0 = wm * 16 + r;
            float* p0 = o + ((size_t)(b * S_ + n * 64 + i0)) * H_ + h * 128 + d;
            *(float2*)p0 = make_float2(oacc[nf][0], oacc[nf][1]);
            *(float2*)(p0 + 8 * H_) = make_float2(oacc[nf][2], oacc[nf][3]);
        }
    }

    // ---- P = u^T k: warp tile 32(m=d) x 64(n=e) ----
    {
        float pc[2][8][4] = {};
#pragma unroll
        for (int ks = 0; ks < 4; ks++) {
            uint32_t af[2][4];
#pragma unroll
            for (int mf = 0; mf < 2; mf++) {
                int dm = wm * 32 + mf * 16;
                int rowj = ks * 16 + ((lane >> 4) & 1) * 8 + (lane & 7);
                int dcol = dm + ((lane >> 3) & 1) * 8;
                ldmAT(af[mf], su + (uint32_t)rowj * PH + dcol * 2);
            }
#pragma unroll
            for (int nf = 0; nf < 8; nf++) {
                int ebase = wn * 64 + nf * 8;
                uint32_t bf[2];
                ldmBT(bf, sk + (uint32_t)(ks * 16 + (lane & 15)) * PH + ebase * 2);
#pragma unroll
                for (int mf = 0; mf < 2; mf++)
                    mma16816(pc[mf][nf], af[mf], bf);
            }
        }
        float* Pp = P + ((size_t)bh * NC_ + n) * (D_ * D_);
#pragma unroll
        for (int mf = 0; mf < 2; mf++)
#pragma unroll
            for (int nf = 0; nf < 8; nf++) {
                int d = wm * 32 + mf * 16 + r;
                int e = wn * 64 + nf * 8 + cb;
                float* pp = Pp + (size_t)d * 128 + e;
                *(float2*)pp = make_float2(pc[mf][nf][0], pc[mf][nf][1]);
                *(float2*)(pp + 8 * 128) = make_float2(pc[mf][nf][2], pc[mf][nf][3]);
            }
    }
}

// ---------------------------------------------------------------------------
// Exclusive prefix over chunks of P per (bh) -> S (fp16); final state -> out
// ---------------------------------------------------------------------------
__global__ __launch_bounds__(256) void prefix_state(
    const float* __restrict__ P, __half* __restrict__ Sh,
    float* __restrict__ out_state)
{
    int bh = blockIdx.x >> 3;
    int part = blockIdx.x & 7;
    int idx = part * 2048 + threadIdx.x * 8;
    float acc[8] = {0, 0, 0, 0, 0, 0, 0, 0};
    const float* base = P + (size_t)bh * NC_ * (D_ * D_) + idx;
    __half* sbase = Sh + (size_t)bh * NC_ * (D_ * D_) + idx;
    for (int nn = 0; nn < NC_; nn++) {
        const float* p = base + (size_t)nn * (D_ * D_);
        float4 p0 = *(const float4*)(p);
        float4 p1 = *(const float4*)(p + 4);
        float4 hv;
        __half2* hp = (__half2*)&hv;
        hp[0] = __floats2half2_rn(acc[0], acc[1]);
        hp[1] = __floats2half2_rn(acc[2], acc[3]);
        hp[2] = __floats2half2_rn(acc[4], acc[5]);
        hp[3] = __floats2half2_rn(acc[6], acc[7]);
        *(float4*)(sbase + (size_t)nn * (D_ * D_)) = hv;
        acc[0] += p0.x; acc[1] += p0.y; acc[2] += p0.z; acc[3] += p0.w;
        acc[4] += p1.x; acc[5] += p1.y; acc[6] += p1.z; acc[7] += p1.w;
    }
    float* qo = out_state + (size_t)bh * (D_ * D_) + idx;
    *(float4*)(qo)     = make_float4(acc[0], acc[1], acc[2], acc[3]);
    *(float4*)(qo + 4) = make_float4(acc[4], acc[5], acc[6], acc[7]);
}

// ---------------------------------------------------------------------------
// Tensorized inter-chunk: oh = fp16(o_intra + q @ S^T)
// ---------------------------------------------------------------------------
#define IN_SMEM (64 * PH + 128 * PH)

__global__ __launch_bounds__(256) void inter_chunk(
    const __half* __restrict__ q, const __half* __restrict__ Sh,
    const float* __restrict__ o, __half* __restrict__ oh)
{
    extern __shared__ char smc[];
    const uint32_t sq = s2u(smc);
    const uint32_t sS = sq + 64 * PH;

    const int n = blockIdx.x, bh = blockIdx.y;
    const int tid = threadIdx.x;
    const int lane = tid & 31, wid = tid >> 5;
    const int wm = wid >> 1, wn = wid & 1;
    const size_t qbase = ((size_t)bh * S_ + n * 64) * D_;
    const __half* Sp = Sh + ((size_t)bh * NC_ + n) * (D_ * D_);

#pragma unroll
    for (int i = 0; i < 4; i++) {
        int v = tid + i * 256;
        int rr = v >> 4, c = v & 15;
        *(float4*)(smc + rr * PH + c * 16) = *(const float4*)(q + qbase + rr * 128 + c * 8);
    }
#pragma unroll
    for (int i = 0; i < 8; i++) {
        int v = tid + i * 256;
        int rr = v >> 4, c = v & 15;
        *(float4*)(smc + 64 * PH + rr * PH + c * 16) = *(const float4*)(Sp + rr * 128 + c * 8);
    }
    __syncthreads();

    float acc[8][4] = {};
#pragma unroll
    for (int ks = 0; ks < 8; ks++) {
        uint32_t af[4];
        ldmA(af, sq + (uint32_t)(wm * 16 + (lane & 15)) * PH
                   + ks * 32 + (lane >> 4) * 16);
#pragma unroll
        for (int nf = 0; nf < 8; nf++) {
            uint32_t bf[2];
            ldmB(bf, sS + (uint32_t)(wn * 64 + nf * 8 + (lane & 7)) * PH
                       + ks * 32 + ((lane >> 3) & 1) * 16);
            mma16816(acc[nf], af, bf);
        }
    }

    const int r = lane >> 2, cb = (lane & 3) * 2;
    const int b = bh >> 4, h = bh & 15;
#pragma unroll
    for (int nf = 0; nf < 8; nf++) {
        int d = wn * 64 + nf * 8 + cb;
        int i0 = wm * 16 + r;
        size_t base = ((size_t)(b * S_ + n * 64 + i0)) * H_ + h * 128 + d;
        float2 pv0 = *(const float2*)(o + base);
        float2 pv1 = *(const float2*)(o + base + 8 * H_);
        *(__half2*)(oh + base) = __floats2half2_rn(pv0.x + acc[nf][0], pv0.y + acc[nf][1]);
        *(__half2*)(oh + base + 8 * H_) = __floats2half2_rn(pv1.x + acc[nf][2], pv1.y + acc[nf][3]);
    }
}

// ---------------------------------------------------------------------------
// Launch
// ---------------------------------------------------------------------------
extern "C" void kernel_launch(void* const* d_in, const int* in_sizes, int n_in,
                              void* d_out, int out_size)
{
    (void)in_sizes; (void)n_in; (void)out_size;
    const float* x  = (const float*)d_in[0];
    const float* Wq = (const float*)d_in[1];
    const float* Wk = (const float*)d_in[2];
    const float* Wv = (const float*)d_in[3];
    const float* Wb = (const float*)d_in[4];
    const float* Wo = (const float*)d_in[5];
    float* out = (float*)d_out;
    float* out_state = out + (size_t)M_ * H_;

    float *po, *pP;
    __half *pqh, *pkh, *pvh, *pbb, *pSh, *pxh, *poh, *pWth;
    cudaGetSymbolAddress((void**)&pqh, g_qh);
    cudaGetSymbolAddress((void**)&pkh, g_kh);
    cudaGetSymbolAddress((void**)&pvh, g_vh);
    cudaGetSymbolAddress((void**)&pbb, g_bb);
    cudaGetSymbolAddress((void**)&po,  g_o);
    cudaGetSymbolAddress((void**)&pP,  g_P);
    cudaGetSymbolAddress((void**)&pSh, g_Sh);
    cudaGetSymbolAddress((void**)&pxh, g_xh);
    cudaGetSymbolAddress((void**)&poh, g_oh);
    cudaGetSymbolAddress((void**)&pWth, g_Wth);

    cudaFuncSetAttribute(tcgemm_proj, cudaFuncAttributeMaxDynamicSharedMemorySize, GEMM_SMEM);
    cudaFuncSetAttribute(tcgemm_out,  cudaFuncAttributeMaxDynamicSharedMemorySize, GEMM_SMEM);
    cudaFuncSetAttribute(chunk_local, cudaFuncAttributeMaxDynamicSharedMemorySize, CL_SMEM);
    cudaFuncSetAttribute(inter_chunk, cudaFuncAttributeMaxDynamicSharedMemorySize, IN_SMEM);

    const size_t WSZ = (size_t)H_ * H_;

    dim3 tg(H_ / 32, H_ / 32, 5), tb(32, 8);
    transpose5<<<tg, tb>>>(Wq, Wk, Wv, Wb, Wo, pWth);

    convert_half<<<(M_ * (H_ / 4)) / 256, 256>>>(x, pxh);

    dim3 gp(H_ / 128, M_ / 128, 4);
    tcgemm_proj<<<gp, 256, GEMM_SMEM>>>(pxh, pWth, pqh, pkh, pvh, pbb);

    dim3 gc(NC_, B_ * NH_);
    chunk_local<<<gc, 256, CL_SMEM>>>(pqh, pkh, pvh, pbb, po, pP);
    prefix_state<<<B_ * NH_ * 8, 256>>>(pP, pSh, out_state);
    inter_chunk<<<gc, 256, IN_SMEM>>>(pqh, pSh, po, poh);

    dim3 go(H_ / 128, M_ / 128);
    tcgemm_out<<<go, 256, GEMM_SMEM>>>(poh, pWth + 4 * WSZ, out);
}